// round 8
// baseline (speedup 1.0000x reference)
#include <cuda_runtime.h>
#include <math.h>

#define Bb 4
#define Tt 2048
#define Dm 1024
#define Ee 6
#define Pp 36
#define DAa 512
#define NCHUNK 32
#define RPC (Tt / NCHUNK)
#define THRESH 0.3f
#define LN_EPS 1e-5f
#define OUT_MAIN (Bb * Tt * Dm)

#define INIT_BLOCKS 1568
#define U_BLOCKS 768
#define COND_SMEM 69920
#define STRM_SMEM 81920

// ---------------- scratch ------------------------------------------------------
__device__ float g_u[Ee * Dm];
__device__ float g_ps[Ee * Bb * NCHUNK];
__device__ float g_pacc[Ee * Bb * NCHUNK * Dm];
__device__ float g_y[Ee * Bb * Dm];
__device__ float g_form[Ee * Bb * Dm];
__device__ float g_c[Pp * Bb * 2 * DAa];
__device__ float g_hpre[Pp * Bb * DAa];
__device__ float g_hs[Pp * Bb * Dm];
__device__ float g_scalepb[Pp * Bb];
__device__ float g_count;
__device__ float g_total[Bb * Dm];
__device__ float g_addition[Bb * Dm];

__device__ __forceinline__ float gelu_exact(float x) {
    return 0.5f * x * (1.0f + erff(x * 0.70710678118654752f));
}

// ---------------- cp.async helpers ----------------------------------------------
__device__ __forceinline__ void cp16(float4* smem_dst, const float4* gsrc) {
    unsigned sa = (unsigned)__cvta_generic_to_shared(smem_dst);
    asm volatile("cp.async.cg.shared.global [%0], [%1], 16;\n" :: "r"(sa), "l"(gsrc));
}
#define CP_COMMIT() asm volatile("cp.async.commit_group;\n" ::: "memory")
#define CP_WAIT2() asm volatile("cp.async.wait_group 2;\n" ::: "memory")
#define CP_WAIT1() asm volatile("cp.async.wait_group 1;\n" ::: "memory")
#define CP_WAIT0() asm volatile("cp.async.wait_group 0;\n" ::: "memory")

// ---------------- init (bias prep) + u, one kernel ------------------------------
__global__ void k_init_u(const float* __restrict__ bv, const float* __restrict__ ba,
                         const float* __restrict__ bb, const float* __restrict__ gb1,
                         const float* __restrict__ sb1, const float* __restrict__ outb,
                         const float* __restrict__ agate,
                         const float* __restrict__ Wk, const float* __restrict__ q) {
    int bid = blockIdx.x;
    if (bid < INIT_BLOCKS) {
        int i = bid * 256 + threadIdx.x;
        if (i == 0) g_count = 0.0f;
        if (i < Ee * Bb * Dm) {
            int e = i / (Bb * Dm);
            g_form[i] = bv[e * Dm + (i % Dm)];
            return;
        }
        i -= Ee * Bb * Dm;
        if (i < Pp * Bb * 1024) {
            int p = i / (Bb * 1024);
            int j = i % 1024;
            g_c[i] = (j < DAa) ? ba[p * DAa + j] : bb[p * DAa + (j - DAa)];
            return;
        }
        i -= Pp * Bb * 1024;
        if (i < Pp * Bb * DAa) {
            int p = i / (Bb * DAa);
            g_hpre[i] = gb1[p * DAa + (i % DAa)];
            return;
        }
        i -= Pp * Bb * DAa;
        if (i < Pp * Bb * Dm) {
            int p = i / (Bb * Dm);
            g_hs[i] = sb1[p * Dm + (i % Dm)];
            return;
        }
        i -= Pp * Bb * Dm;
        if (i < Bb * Dm) { g_total[i] = 0.0f; return; }
        i -= Bb * Dm;
        if (i < Bb * Dm) g_addition[i] = outb[i & (Dm - 1)] * (*agate);
        return;
    }
    int warp = (bid - INIT_BLOCKS) * 8 + (threadIdx.x >> 5);
    int lane = threadIdx.x & 31;
    if (warp >= Ee * Dm) return;
    int e = warp / Dm, d = warp % Dm;
    const float4* w4 = reinterpret_cast<const float4*>(Wk + ((size_t)e * Dm + d) * Dm);
    const float4* q4 = reinterpret_cast<const float4*>(q + e * Dm);
    float s = 0.0f;
#pragma unroll
    for (int f = lane; f < Dm / 4; f += 32) {
        float4 a = w4[f], b = q4[f];
        s += a.x * b.x + a.y * b.y + a.z * b.z + a.w * b.w;
    }
#pragma unroll
    for (int o = 16; o; o >>= 1) s += __shfl_down_sync(0xffffffffu, s, o);
    if (!lane) g_u[warp] = s * 0.03125f;
}

// ---------------- condenser: cp.async pipelined, warp-per-row -------------------
__global__ void __launch_bounds__(256) k_condense(const float* __restrict__ eo,
                                                  const float* __restrict__ ew) {
    extern __shared__ float4 dyn4[];
    float4* buf  = dyn4;
    float4* s_u  = dyn4 + 4096;
    float*  s_w  = (float*)(dyn4 + 4352);
    float*  s_sum = s_w + 64;
    int bid = blockIdx.x;
    int chunk = bid % NCHUNK;
    int eb = bid / NCHUNK;
    int e = eb / Bb, b = eb % Bb;
    int tid = threadIdx.x;
    int lane = tid & 31, warp = tid >> 5;
    if (tid < RPC)
        s_w[tid] = ew[((size_t)b * Tt + (size_t)chunk * RPC + tid) * Ee + e];
    s_u[tid] = reinterpret_cast<const float4*>(g_u)[e * 256 + tid];
    const float4* xbase = reinterpret_cast<const float4*>(eo) +
        (((size_t)e * Bb + b) * Tt + (size_t)chunk * RPC) * 256;
#pragma unroll
    for (int k = 0; k < 8; k++) cp16(buf + k * 256 + tid, xbase + (size_t)k * 256 + tid);
    CP_COMMIT();
#pragma unroll
    for (int k = 0; k < 8; k++) cp16(buf + 2048 + k * 256 + tid, xbase + (size_t)(8 + k) * 256 + tid);
    CP_COMMIT();
    __syncthreads();

    float ssum = 0.0f;
    float4 acc[8] = {};
    for (int t = 0; t < 8; t++) {
        if (t == 7) { CP_WAIT0(); } else { CP_WAIT1(); }
        __syncthreads();
        const float4* bp = buf + (t & 1) * 2048;
        float4 xv[8];
#pragma unroll
        for (int k = 0; k < 8; k++) xv[k] = bp[warp * 256 + lane + 32 * k];
        float d = 0.0f;
#pragma unroll
        for (int k = 0; k < 8; k++) {
            float4 us = s_u[lane + 32 * k];
            d += xv[k].x * us.x + xv[k].y * us.y + xv[k].z * us.z + xv[k].w * us.w;
        }
#pragma unroll
        for (int o = 16; o; o >>= 1) d += __shfl_xor_sync(0xffffffffu, d, o);
        float w = s_w[t * 8 + warp];
        float eexp = __expf(d * w); // |d*w| << 1: max-free softmax exact here
        ssum += eexp;
        float cf = eexp * w;
#pragma unroll
        for (int k = 0; k < 8; k++) {
            acc[k].x += cf * xv[k].x; acc[k].y += cf * xv[k].y;
            acc[k].z += cf * xv[k].z; acc[k].w += cf * xv[k].w;
        }
        __syncthreads();
        if (t < 6) {
#pragma unroll
            for (int k = 0; k < 8; k++)
                cp16(buf + (t & 1) * 2048 + k * 256 + tid,
                     xbase + (size_t)((t + 2) * 8 + k) * 256 + tid);
            CP_COMMIT();
        }
    }
#pragma unroll
    for (int k = 0; k < 8; k++) buf[warp * 256 + lane + 32 * k] = acc[k];
    if (lane == 0) s_sum[warp] = ssum;
    __syncthreads();
    float4 tot = {0.f, 0.f, 0.f, 0.f};
#pragma unroll
    for (int w = 0; w < 8; w++) {
        float4 a = buf[w * 256 + tid];
        tot.x += a.x; tot.y += a.y; tot.z += a.z; tot.w += a.w;
    }
    reinterpret_cast<float4*>(g_pacc)[(size_t)bid * 256 + tid] = tot;
    if (tid == 0) {
        float t = 0;
#pragma unroll
        for (int w = 0; w < 8; w++) t += s_sum[w];
        g_ps[bid] = t;
    }
}

// ---------------- combine partials -> y (192 blocks) ----------------------------
__global__ void __launch_bounds__(256) k_combine() {
    int eb = blockIdx.x >> 3, q = blockIdx.x & 7;
    int tid = threadIdx.x;
    int col = (tid & 31) + q * 32, cg = tid >> 5; // 8 chunk-groups of 4
    __shared__ float4 s_acc[7][32];
    float S = 0.0f;
#pragma unroll
    for (int c = 0; c < NCHUNK; c++) S += g_ps[eb * NCHUNK + c];
    float4 y = {0.f, 0.f, 0.f, 0.f};
#pragma unroll
    for (int k = 0; k < 4; k++) {
        int pidx = eb * NCHUNK + cg * 4 + k;
        float4 a = reinterpret_cast<const float4*>(g_pacc)[(size_t)pidx * 256 + col];
        y.x += a.x; y.y += a.y; y.z += a.z; y.w += a.w;
    }
    if (cg > 0) s_acc[cg - 1][tid & 31] = y;
    __syncthreads();
    if (cg == 0) {
#pragma unroll
        for (int j = 0; j < 7; j++) {
            float4 a = s_acc[j][tid & 31];
            y.x += a.x; y.y += a.y; y.z += a.z; y.w += a.w;
        }
        float inv = 1.0f / S;
        y.x *= inv; y.y *= inv; y.z *= inv; y.w *= inv;
        reinterpret_cast<float4*>(g_y)[(size_t)eb * 256 + col] = y;
    }
}

// ---------------- 4-stage streaming GEMV (16 KB tiles, 3 in flight) -------------
// Tile = 1024 float4. C4=256: 4 rows/tile; C4=128: 8 rows/tile (2 row-groups).
template <int NT, int C4>
__device__ __forceinline__ void gemv_streamT(const float4* __restrict__ W0,
                                             const float* s_in, int din0,
                                             float4* buf, int tid, float4 acc[Bb]) {
#pragma unroll
    for (int s = 0; s < 3; s++) {
#pragma unroll
        for (int k = 0; k < 4; k++)
            cp16(buf + s * 1024 + k * 256 + tid, W0 + (size_t)s * 1024 + k * 256 + tid);
        CP_COMMIT();
    }
    int rg = (C4 == 128) ? (tid >> 7) : 0;
#pragma unroll
    for (int t = 0; t < NT; t++) {
        if (t < NT - 2) { CP_WAIT2(); }
        else if (t == NT - 2) { CP_WAIT1(); }
        else { CP_WAIT0(); }
        __syncthreads();
        const float4* bp = buf + (t & 3) * 1024;
        float4 w[4];
#pragma unroll
        for (int k = 0; k < 4; k++) w[k] = bp[k * 256 + tid];
#pragma unroll
        for (int k = 0; k < 4; k++) {
            int xi = (C4 == 256) ? (din0 + t * 4 + k) : (din0 + t * 8 + 2 * k + rg);
#pragma unroll
            for (int b = 0; b < Bb; b++) {
                float x = s_in[b * 1024 + xi];
                acc[b].x += x * w[k].x; acc[b].y += x * w[k].y;
                acc[b].z += x * w[k].z; acc[b].w += x * w[k].w;
            }
        }
        __syncthreads();
        if (t + 3 < NT) {
#pragma unroll
            for (int k = 0; k < 4; k++)
                cp16(buf + ((t + 3) & 3) * 1024 + k * 256 + tid,
                     W0 + (size_t)(t + 3) * 1024 + k * 256 + tid);
            CP_COMMIT();
        }
    }
}

// ---------------- formulas = y @ Wv (192 blocks, 32 rows each) -------------------
__global__ void __launch_bounds__(256) k_form(const float* __restrict__ Wv) {
    extern __shared__ float4 dyn4[];
    float4* buf = dyn4;
    float* s_in = (float*)(dyn4 + 4096);
    int e = blockIdx.x >> 5, ds = blockIdx.x & 31;
    int tid = threadIdx.x;
#pragma unroll
    for (int k = tid; k < Bb * Dm / 4; k += 256)
        reinterpret_cast<float4*>(s_in)[k] =
            reinterpret_cast<const float4*>(g_y + (size_t)e * Bb * Dm)[k];
    int d0 = ds * 32;
    const float4* W0 = reinterpret_cast<const float4*>(Wv + (size_t)e * Dm * Dm) +
                       (size_t)d0 * 256;
    float4 acc[Bb] = {};
    __syncthreads();
    gemv_streamT<8, 256>(W0, s_in, d0, buf, tid, acc);
#pragma unroll
    for (int b = 0; b < Bb; b++) {
        float* dst = g_form + ((size_t)e * Bb + b) * Dm + 4 * tid;
        atomicAdd(dst + 0, acc[b].x); atomicAdd(dst + 1, acc[b].y);
        atomicAdd(dst + 2, acc[b].z); atomicAdd(dst + 3, acc[b].w);
    }
}

// ---------------- pair projections: c[p] = [fa@Wa | fb@Wb] ----------------------
// grid = Pp*16 = 576, 128 rows each
__global__ void __launch_bounds__(256) k_pair_ab(const float* __restrict__ Wa,
                                                 const float* __restrict__ Wb) {
    extern __shared__ float4 dyn4[];
    float4* buf = dyn4;
    float* s_in = (float*)(dyn4 + 4096);
    int bid = blockIdx.x;
    int ds = bid & 7;
    int half = (bid >> 3) & 1;
    int p = bid >> 4;
    int src = half ? (p % Ee) : (p / Ee);
    int tid = threadIdx.x;
    int col = tid & 127;
#pragma unroll
    for (int k = tid; k < Bb * Dm / 4; k += 256)
        reinterpret_cast<float4*>(s_in)[k] =
            reinterpret_cast<const float4*>(g_form + (size_t)src * Bb * Dm)[k];
    int d0 = ds * 128;
    const float4* W0 = reinterpret_cast<const float4*>(
        (half ? Wb : Wa) + (size_t)p * Dm * DAa) + (size_t)d0 * 128;
    float4 acc[Bb] = {};
    __syncthreads();
    gemv_streamT<16, 128>(W0, s_in, d0, buf, tid, acc);
#pragma unroll
    for (int b = 0; b < Bb; b++) {
        float* dst = g_c + ((size_t)p * Bb + b) * 1024 + half * DAa + 4 * col;
        atomicAdd(dst + 0, acc[b].x); atomicAdd(dst + 1, acc[b].y);
        atomicAdd(dst + 2, acc[b].z); atomicAdd(dst + 3, acc[b].w);
    }
}

// ---------------- fused syn1 + gate1 --------------------------------------------
// grid = Pp*24: t<16 -> syn1 (64 rows, C4=256); t>=16 -> gate1 (128 rows, C4=128)
__global__ void __launch_bounds__(256) k_mlp1(const float* __restrict__ sW1,
                                              const float* __restrict__ gW1) {
    extern __shared__ float4 dyn4[];
    float4* buf = dyn4;
    float* s_in = (float*)(dyn4 + 4096);
    int bid = blockIdx.x;
    int t = bid % 24;
    int p = bid / 24;
    int tid = threadIdx.x;
#pragma unroll
    for (int k = tid; k < Bb * 1024 / 4; k += 256)
        reinterpret_cast<float4*>(s_in)[k] =
            reinterpret_cast<const float4*>(g_c + (size_t)p * Bb * 1024)[k];
    float4 acc[Bb] = {};
    __syncthreads();
    if (t < 16) {
        int d0 = t * 64;
        const float4* W0 = reinterpret_cast<const float4*>(sW1 + (size_t)p * 1024 * Dm) +
                           (size_t)d0 * 256;
        gemv_streamT<16, 256>(W0, s_in, d0, buf, tid, acc);
#pragma unroll
        for (int b = 0; b < Bb; b++) {
            float* dst = g_hs + ((size_t)p * Bb + b) * Dm + 4 * tid;
            atomicAdd(dst + 0, acc[b].x); atomicAdd(dst + 1, acc[b].y);
            atomicAdd(dst + 2, acc[b].z); atomicAdd(dst + 3, acc[b].w);
        }
    } else {
        int ds = t - 16;
        int col = tid & 127;
        int d0 = ds * 128;
        const float4* W0 = reinterpret_cast<const float4*>(gW1 + (size_t)p * 1024 * DAa) +
                           (size_t)d0 * 128;
        gemv_streamT<16, 128>(W0, s_in, d0, buf, tid, acc);
#pragma unroll
        for (int b = 0; b < Bb; b++) {
            float* dst = g_hpre + ((size_t)p * Bb + b) * DAa + 4 * col;
            atomicAdd(dst + 0, acc[b].x); atomicAdd(dst + 1, acc[b].y);
            atomicAdd(dst + 2, acc[b].z); atomicAdd(dst + 3, acc[b].w);
        }
    }
}

// ---------------- strength + scalepb + bias-total + aux out ---------------------
__global__ void __launch_bounds__(128) k_strength(const float* __restrict__ gW2,
                                                  const float* __restrict__ gb2,
                                                  const float* __restrict__ pg,
                                                  const float* __restrict__ sb2,
                                                  float* __restrict__ out, int out_size) {
    int p = blockIdx.x, tid = threadIdx.x;
    float part[Bb] = {0.f, 0.f, 0.f, 0.f};
    for (int a = tid; a < DAa; a += 128) {
        float w2 = gW2[p * DAa + a];
#pragma unroll
        for (int b = 0; b < Bb; b++) {
            float h = g_hpre[((size_t)p * Bb + b) * DAa + a];
            part[b] += gelu_exact(h) * w2;
        }
    }
    __shared__ float s_red[Bb][4];
    __shared__ float s_sc[Bb];
#pragma unroll
    for (int b = 0; b < Bb; b++) {
        float v = part[b];
#pragma unroll
        for (int o = 16; o; o >>= 1) v += __shfl_down_sync(0xffffffffu, v, o);
        if ((tid & 31) == 0) s_red[b][tid >> 5] = v;
    }
    __syncthreads();
    if (tid == 0) {
        float avg = 0.0f;
        float st[Bb];
#pragma unroll
        for (int b = 0; b < Bb; b++) {
            float d = s_red[b][0] + s_red[b][1] + s_red[b][2] + s_red[b][3] + gb2[p];
            st[b] = 1.0f / (1.0f + expf(-d));
            avg += st[b];
        }
        avg *= 0.25f;
        if (out_size >= OUT_MAIN + Pp + 1) out[OUT_MAIN + p] = avg;
        float mk = 0.0f;
        if (avg > THRESH) { mk = pg[p]; atomicAdd(&g_count, 1.0f); }
#pragma unroll
        for (int b = 0; b < Bb; b++) {
            float sc = mk * st[b];
            g_scalepb[p * Bb + b] = sc;
            s_sc[b] = sc;
        }
    }
    __syncthreads();
    float sc0 = s_sc[0], sc1 = s_sc[1], sc2 = s_sc[2], sc3 = s_sc[3];
    for (int j = tid; j < Dm; j += 128) {
        float bias = sb2[p * Dm + j];
        atomicAdd(&g_total[0 * Dm + j], sc0 * bias);
        atomicAdd(&g_total[1 * Dm + j], sc1 * bias);
        atomicAdd(&g_total[2 * Dm + j], sc2 * bias);
        atomicAdd(&g_total[3 * Dm + j], sc3 * bias);
    }
}

// ---------------- total += scale_pb * (gelu(hs) @ syn_W2) -----------------------
// grid = Pp*16 = 576 (64 rows each)
__global__ void __launch_bounds__(256) k_syn2(const float* __restrict__ sW2) {
    extern __shared__ float4 dyn4[];
    float4* buf = dyn4;
    float* s_in = (float*)(dyn4 + 4096);
    int bid = blockIdx.x;
    int ds = bid & 15;
    int p = bid >> 4;
    int tid = threadIdx.x;
#pragma unroll
    for (int k = tid; k < Bb * Dm / 4; k += 256) {
        float4 v = reinterpret_cast<const float4*>(g_hs + (size_t)p * Bb * Dm)[k];
        v.x = gelu_exact(v.x); v.y = gelu_exact(v.y);
        v.z = gelu_exact(v.z); v.w = gelu_exact(v.w);
        reinterpret_cast<float4*>(s_in)[k] = v;
    }
    int d0 = ds * 64;
    const float4* W0 = reinterpret_cast<const float4*>(sW2 + (size_t)p * Dm * Dm) +
                       (size_t)d0 * 256;
    float4 acc[Bb] = {};
    __syncthreads();
    gemv_streamT<16, 256>(W0, s_in, d0, buf, tid, acc);
#pragma unroll
    for (int b = 0; b < Bb; b++) {
        float sc = g_scalepb[p * Bb + b];
        float* dst = g_total + b * Dm + 4 * tid;
        atomicAdd(dst + 0, acc[b].x * sc); atomicAdd(dst + 1, acc[b].y * sc);
        atomicAdd(dst + 2, acc[b].z * sc); atomicAdd(dst + 3, acc[b].w * sc);
    }
}

// ---------------- fused LN + projection ------------------------------------------
__global__ void __launch_bounds__(256) k_ln_proj(const float* __restrict__ gamma,
                                                 const float* __restrict__ beta,
                                                 const float* __restrict__ out_W,
                                                 const float* __restrict__ ag_p,
                                                 float* __restrict__ out, int out_size) {
    int ds = blockIdx.x;
    int tid = threadIdx.x;
    __shared__ float s_norm[Bb * Dm];
    __shared__ float s_red[8];
    __shared__ float s_stat;
    float inv_cnt = 1.0f / fmaxf(g_count, 1.0f);
    float ag = *ag_p;
    if (ds == 0 && tid == 0 && out_size >= OUT_MAIN + Pp + 1)
        out[OUT_MAIN + Pp] = g_count;
    float4 ga = reinterpret_cast<const float4*>(gamma)[tid];
    float4 be = reinterpret_cast<const float4*>(beta)[tid];
    for (int b = 0; b < Bb; b++) {
        float4 v = reinterpret_cast<const float4*>(g_total + b * Dm)[tid];
        v.x *= inv_cnt; v.y *= inv_cnt; v.z *= inv_cnt; v.w *= inv_cnt;
        float lsum = v.x + v.y + v.z + v.w;
#pragma unroll
        for (int o = 16; o; o >>= 1) lsum += __shfl_down_sync(0xffffffffu, lsum, o);
        if ((tid & 31) == 0) s_red[tid >> 5] = lsum;
        __syncthreads();
        if (tid == 0) {
            float t = 0;
#pragma unroll
            for (int k = 0; k < 8; k++) t += s_red[k];
            s_stat = t * (1.0f / Dm);
        }
        __syncthreads();
        float mu = s_stat;
        __syncthreads();
        float dx = v.x - mu, dy = v.y - mu, dz = v.z - mu, dw = v.w - mu;
        float lsq = dx * dx + dy * dy + dz * dz + dw * dw;
#pragma unroll
        for (int o = 16; o; o >>= 1) lsq += __shfl_xor_sync(0xffffffffu, lsq, o);
        if ((tid & 31) == 0) s_red[tid >> 5] = lsq;
        __syncthreads();
        if (tid == 0) {
            float t = 0;
#pragma unroll
            for (int k = 0; k < 8; k++) t += s_red[k];
            s_stat = t * (1.0f / Dm);
        }
        __syncthreads();
        float rstd = rsqrtf(s_stat + LN_EPS);
        __syncthreads();
        float4 nv;
        nv.x = dx * rstd * ga.x + be.x;
        nv.y = dy * rstd * ga.y + be.y;
        nv.z = dz * rstd * ga.z + be.z;
        nv.w = dw * rstd * ga.w + be.w;
        reinterpret_cast<float4*>(s_norm + b * Dm)[tid] = nv;
    }
    __syncthreads();
    const float4* Wp = reinterpret_cast<const float4*>(out_W) +
                       (size_t)(ds * 32) * 256 + tid;
    float4 acc[Bb] = {};
#pragma unroll 4
    for (int dd = 0; dd < 32; dd++) {
        float4 w = Wp[(size_t)dd * 256];
#pragma unroll
        for (int b = 0; b < Bb; b++) {
            float x = s_norm[b * Dm + ds * 32 + dd];
            acc[b].x += x * w.x; acc[b].y += x * w.y;
            acc[b].z += x * w.z; acc[b].w += x * w.w;
        }
    }
#pragma unroll
    for (int b = 0; b < Bb; b++) {
        float* dst = g_addition + b * Dm + 4 * tid;
        atomicAdd(dst + 0, acc[b].x * ag); atomicAdd(dst + 1, acc[b].y * ag);
        atomicAdd(dst + 2, acc[b].z * ag); atomicAdd(dst + 3, acc[b].w * ag);
    }
}

// ---------------- output = bridge + addition -------------------------------------
__global__ void __launch_bounds__(256) k_output(const float* __restrict__ bridge,
                                                float* __restrict__ out) {
    size_t i4 = (size_t)blockIdx.x * 256 + threadIdx.x;
    if (i4 >= (size_t)OUT_MAIN / 4) return;
    float4 br = reinterpret_cast<const float4*>(bridge)[i4];
    int b = (int)(i4 >> 19);
    int d4 = (int)(i4 & 255);
    if (g_count > 0.0f) {
        float4 ad = reinterpret_cast<const float4*>(g_addition)[b * 256 + d4];
        br.x += ad.x; br.y += ad.y; br.z += ad.z; br.w += ad.w;
    }
    reinterpret_cast<float4*>(out)[i4] = br;
}

// ---------------- launch ----------------------------------------------------------
extern "C" void kernel_launch(void* const* d_in, const int* in_sizes, int n_in,
                              void* d_out, int out_size) {
    const float* bridge = (const float*)d_in[0];
    const float* eo     = (const float*)d_in[1];
    const float* ew     = (const float*)d_in[2];
    const float* q      = (const float*)d_in[3];
    const float* Wk     = (const float*)d_in[4];
    const float* Wv     = (const float*)d_in[6];
    const float* bv     = (const float*)d_in[7];
    const float* Wa     = (const float*)d_in[8];
    const float* ba     = (const float*)d_in[9];
    const float* Wb     = (const float*)d_in[10];
    const float* bb     = (const float*)d_in[11];
    const float* gW1    = (const float*)d_in[12];
    const float* gb1    = (const float*)d_in[13];
    const float* gW2    = (const float*)d_in[14];
    const float* gb2    = (const float*)d_in[15];
    const float* sW1    = (const float*)d_in[16];
    const float* sb1    = (const float*)d_in[17];
    const float* sW2    = (const float*)d_in[18];
    const float* sb2    = (const float*)d_in[19];
    const float* pg     = (const float*)d_in[20];
    const float* gamma  = (const float*)d_in[21];
    const float* beta   = (const float*)d_in[22];
    const float* outW   = (const float*)d_in[23];
    const float* outb   = (const float*)d_in[24];
    const float* agate  = (const float*)d_in[25];
    float* out = (float*)d_out;

    cudaFuncSetAttribute(k_condense, cudaFuncAttributeMaxDynamicSharedMemorySize, COND_SMEM);
    cudaFuncSetAttribute(k_form,     cudaFuncAttributeMaxDynamicSharedMemorySize, STRM_SMEM);
    cudaFuncSetAttribute(k_pair_ab,  cudaFuncAttributeMaxDynamicSharedMemorySize, STRM_SMEM);
    cudaFuncSetAttribute(k_mlp1,     cudaFuncAttributeMaxDynamicSharedMemorySize, STRM_SMEM);
    cudaFuncSetAttribute(k_syn2,     cudaFuncAttributeMaxDynamicSharedMemorySize, STRM_SMEM);

    k_init_u<<<INIT_BLOCKS + U_BLOCKS, 256>>>(bv, ba, bb, gb1, sb1, outb, agate, Wk, q);
    k_condense<<<Ee * Bb * NCHUNK, 256, COND_SMEM>>>(eo, ew);
    k_combine<<<Ee * Bb * 8, 256>>>();
    k_form<<<Ee * 32, 256, STRM_SMEM>>>(Wv);
    k_pair_ab<<<Pp * 16, 256, STRM_SMEM>>>(Wa, Wb);
    k_mlp1<<<Pp * 24, 256, STRM_SMEM>>>(sW1, gW1);
    k_strength<<<Pp, 128>>>(gW2, gb2, pg, sb2, out, out_size);
    k_syn2<<<Pp * 16, 256, STRM_SMEM>>>(sW2);
    k_ln_proj<<<32, 256>>>(gamma, beta, outW, agate, out, out_size);
    k_output<<<(OUT_MAIN / 4 + 255) / 256, 256>>>(bridge, out);
}

// round 9
// speedup vs baseline: 1.0192x; 1.0192x over previous
#include <cuda_runtime.h>
#include <math.h>

#define Bb 4
#define Tt 2048
#define Dm 1024
#define Ee 6
#define Pp 36
#define DAa 512
#define NCHUNK 32
#define RPC (Tt / NCHUNK)
#define THRESH 0.3f
#define LN_EPS 1e-5f
#define OUT_MAIN (Bb * Tt * Dm)

#define INIT_BLOCKS 1568
#define U_BLOCKS 768
#define COND_SMEM 69920
#define STRM_SMEM 81920

// ---------------- scratch ------------------------------------------------------
__device__ float g_u[Ee * Dm];
__device__ float g_ps[Ee * Bb * NCHUNK];
__device__ float g_pacc[Ee * Bb * NCHUNK * Dm];
__device__ float g_y[Ee * Bb * Dm];
__device__ float g_form[Ee * Bb * Dm];
__device__ float g_c[Pp * Bb * 2 * DAa];
__device__ float g_hpre[Pp * Bb * DAa];
__device__ float g_hs[Pp * Bb * Dm];
__device__ float g_scalepb[Pp * Bb];
__device__ float g_count;
__device__ float g_total[Bb * Dm];
__device__ float g_addition[Bb * Dm];

__device__ __forceinline__ float gelu_exact(float x) {
    return 0.5f * x * (1.0f + erff(x * 0.70710678118654752f));
}

// ---------------- cp.async helpers ----------------------------------------------
// "memory" clobber: compiler must not move smem reads across the async-copy issue.
__device__ __forceinline__ void cp16(float4* smem_dst, const float4* gsrc) {
    unsigned sa = (unsigned)__cvta_generic_to_shared(smem_dst);
    asm volatile("cp.async.cg.shared.global [%0], [%1], 16;\n"
                 :: "r"(sa), "l"(gsrc) : "memory");
}
#define CP_COMMIT() asm volatile("cp.async.commit_group;\n" ::: "memory")
#define CP_WAIT2() asm volatile("cp.async.wait_group 2;\n" ::: "memory")
#define CP_WAIT1() asm volatile("cp.async.wait_group 1;\n" ::: "memory")
#define CP_WAIT0() asm volatile("cp.async.wait_group 0;\n" ::: "memory")

// ---------------- init (bias prep) + u, one kernel ------------------------------
__global__ void k_init_u(const float* __restrict__ bv, const float* __restrict__ ba,
                         const float* __restrict__ bb, const float* __restrict__ gb1,
                         const float* __restrict__ sb1, const float* __restrict__ outb,
                         const float* __restrict__ agate,
                         const float* __restrict__ Wk, const float* __restrict__ q) {
    int bid = blockIdx.x;
    if (bid < INIT_BLOCKS) {
        int i = bid * 256 + threadIdx.x;
        if (i == 0) g_count = 0.0f;
        if (i < Ee * Bb * Dm) {
            int e = i / (Bb * Dm);
            g_form[i] = bv[e * Dm + (i % Dm)];
            return;
        }
        i -= Ee * Bb * Dm;
        if (i < Pp * Bb * 1024) {
            int p = i / (Bb * 1024);
            int j = i % 1024;
            g_c[i] = (j < DAa) ? ba[p * DAa + j] : bb[p * DAa + (j - DAa)];
            return;
        }
        i -= Pp * Bb * 1024;
        if (i < Pp * Bb * DAa) {
            int p = i / (Bb * DAa);
            g_hpre[i] = gb1[p * DAa + (i % DAa)];
            return;
        }
        i -= Pp * Bb * DAa;
        if (i < Pp * Bb * Dm) {
            int p = i / (Bb * Dm);
            g_hs[i] = sb1[p * Dm + (i % Dm)];
            return;
        }
        i -= Pp * Bb * Dm;
        if (i < Bb * Dm) { g_total[i] = 0.0f; return; }
        i -= Bb * Dm;
        if (i < Bb * Dm) g_addition[i] = outb[i & (Dm - 1)] * (*agate);
        return;
    }
    int warp = (bid - INIT_BLOCKS) * 8 + (threadIdx.x >> 5);
    int lane = threadIdx.x & 31;
    if (warp >= Ee * Dm) return;
    int e = warp / Dm, d = warp % Dm;
    const float4* w4 = reinterpret_cast<const float4*>(Wk + ((size_t)e * Dm + d) * Dm);
    const float4* q4 = reinterpret_cast<const float4*>(q + e * Dm);
    float s = 0.0f;
#pragma unroll
    for (int f = lane; f < Dm / 4; f += 32) {
        float4 a = w4[f], b = q4[f];
        s += a.x * b.x + a.y * b.y + a.z * b.z + a.w * b.w;
    }
#pragma unroll
    for (int o = 16; o; o >>= 1) s += __shfl_down_sync(0xffffffffu, s, o);
    if (!lane) g_u[warp] = s * 0.03125f;
}

// ---------------- condenser: warp-self-contained cp.async pipeline --------------
// Each warp copies and consumes its own row (t*8+warp); no block barriers in loop.
__global__ void __launch_bounds__(256) k_condense(const float* __restrict__ eo,
                                                  const float* __restrict__ ew) {
    extern __shared__ float4 dyn4[];
    float4* buf  = dyn4;                   // 2 stages x 8 warps x 256 float4
    float4* s_u  = dyn4 + 4096;            // 256 float4
    float*  s_w  = (float*)(dyn4 + 4352);  // 64
    float*  s_sum = s_w + 64;              // 8
    int bid = blockIdx.x;
    int chunk = bid % NCHUNK;
    int eb = bid / NCHUNK;
    int e = eb / Bb, b = eb % Bb;
    int tid = threadIdx.x;
    int lane = tid & 31, warp = tid >> 5;
    if (tid < RPC)
        s_w[tid] = ew[((size_t)b * Tt + (size_t)chunk * RPC + tid) * Ee + e];
    s_u[tid] = reinterpret_cast<const float4*>(g_u)[e * 256 + tid];
    const float4* xbase = reinterpret_cast<const float4*>(eo) +
        (((size_t)e * Bb + b) * Tt + (size_t)chunk * RPC) * 256;
    // prologue: warp's rows 0,1 (global rows warp, warp+8)
#pragma unroll
    for (int k = 0; k < 8; k++)
        cp16(buf + warp * 256 + lane + 32 * k, xbase + (size_t)warp * 256 + lane + 32 * k);
    CP_COMMIT();
#pragma unroll
    for (int k = 0; k < 8; k++)
        cp16(buf + 2048 + warp * 256 + lane + 32 * k,
             xbase + (size_t)(8 + warp) * 256 + lane + 32 * k);
    CP_COMMIT();
    __syncthreads(); // s_w / s_u visible

    float ssum = 0.0f;
    float4 acc[8] = {};
#pragma unroll
    for (int t = 0; t < 8; t++) {
        if (t == 7) { CP_WAIT0(); } else { CP_WAIT1(); }
        const float4* bp = buf + (t & 1) * 2048 + warp * 256;
        float4 xv[8];
#pragma unroll
        for (int k = 0; k < 8; k++) xv[k] = bp[lane + 32 * k];
        float d = 0.0f;
#pragma unroll
        for (int k = 0; k < 8; k++) {
            float4 us = s_u[lane + 32 * k];
            d += xv[k].x * us.x + xv[k].y * us.y + xv[k].z * us.z + xv[k].w * us.w;
        }
#pragma unroll
        for (int o = 16; o; o >>= 1) d += __shfl_xor_sync(0xffffffffu, d, o);
        float w = s_w[t * 8 + warp];
        float eexp = __expf(d * w); // |d*w| << 1: max-free softmax exact here
        ssum += eexp;
        float cf = eexp * w;
#pragma unroll
        for (int k = 0; k < 8; k++) {
            acc[k].x += cf * xv[k].x; acc[k].y += cf * xv[k].y;
            acc[k].z += cf * xv[k].z; acc[k].w += cf * xv[k].w;
        }
        if (t < 6) {
#pragma unroll
            for (int k = 0; k < 8; k++)
                cp16(buf + (t & 1) * 2048 + warp * 256 + lane + 32 * k,
                     xbase + (size_t)((t + 2) * 8 + warp) * 256 + lane + 32 * k);
            CP_COMMIT();
        }
    }
    // cross-warp reduce (all async copies complete per-thread by WAIT0)
#pragma unroll
    for (int k = 0; k < 8; k++) buf[warp * 256 + lane + 32 * k] = acc[k];
    if (lane == 0) s_sum[warp] = ssum;
    __syncthreads();
    float4 tot = {0.f, 0.f, 0.f, 0.f};
#pragma unroll
    for (int w = 0; w < 8; w++) {
        float4 a = buf[w * 256 + tid];
        tot.x += a.x; tot.y += a.y; tot.z += a.z; tot.w += a.w;
    }
    reinterpret_cast<float4*>(g_pacc)[(size_t)bid * 256 + tid] = tot;
    if (tid == 0) {
        float t = 0;
#pragma unroll
        for (int w = 0; w < 8; w++) t += s_sum[w];
        g_ps[bid] = t;
    }
}

// ---------------- combine partials -> y (192 blocks) ----------------------------
__global__ void __launch_bounds__(256) k_combine() {
    int eb = blockIdx.x >> 3, q = blockIdx.x & 7;
    int tid = threadIdx.x;
    int col = (tid & 31) + q * 32, cg = tid >> 5;
    __shared__ float4 s_acc[7][32];
    float S = 0.0f;
#pragma unroll
    for (int c = 0; c < NCHUNK; c++) S += g_ps[eb * NCHUNK + c];
    float4 y = {0.f, 0.f, 0.f, 0.f};
#pragma unroll
    for (int k = 0; k < 4; k++) {
        int pidx = eb * NCHUNK + cg * 4 + k;
        float4 a = reinterpret_cast<const float4*>(g_pacc)[(size_t)pidx * 256 + col];
        y.x += a.x; y.y += a.y; y.z += a.z; y.w += a.w;
    }
    if (cg > 0) s_acc[cg - 1][tid & 31] = y;
    __syncthreads();
    if (cg == 0) {
#pragma unroll
        for (int j = 0; j < 7; j++) {
            float4 a = s_acc[j][tid & 31];
            y.x += a.x; y.y += a.y; y.z += a.z; y.w += a.w;
        }
        float inv = 1.0f / S;
        y.x *= inv; y.y *= inv; y.z *= inv; y.w *= inv;
        reinterpret_cast<float4*>(g_y)[(size_t)eb * 256 + col] = y;
    }
}

// ---------------- 4-stage streaming GEMV, barrier-free (self-produced tiles) ----
// Tile = 1024 float4. Thread tid copies & consumes buf[slot*1024 + k*256 + tid].
template <int NT, int C4>
__device__ __forceinline__ void gemv_streamT(const float4* __restrict__ W0,
                                             const float* s_in, int din0,
                                             float4* buf, int tid, float4 acc[Bb]) {
#pragma unroll
    for (int s = 0; s < 3; s++) {
#pragma unroll
        for (int k = 0; k < 4; k++)
            cp16(buf + s * 1024 + k * 256 + tid, W0 + (size_t)s * 1024 + k * 256 + tid);
        CP_COMMIT();
    }
    int rg = (C4 == 128) ? (tid >> 7) : 0;
#pragma unroll
    for (int t = 0; t < NT; t++) {
        if (t < NT - 2) { CP_WAIT2(); }
        else if (t == NT - 2) { CP_WAIT1(); }
        else { CP_WAIT0(); }
        const float4* bp = buf + (t & 3) * 1024;
        float4 w[4];
#pragma unroll
        for (int k = 0; k < 4; k++) w[k] = bp[k * 256 + tid];
#pragma unroll
        for (int k = 0; k < 4; k++) {
            int xi = (C4 == 256) ? (din0 + t * 4 + k) : (din0 + t * 8 + 2 * k + rg);
#pragma unroll
            for (int b = 0; b < Bb; b++) {
                float x = s_in[b * 1024 + xi];
                acc[b].x += x * w[k].x; acc[b].y += x * w[k].y;
                acc[b].z += x * w[k].z; acc[b].w += x * w[k].w;
            }
        }
        if (t + 3 < NT) {
#pragma unroll
            for (int k = 0; k < 4; k++)
                cp16(buf + ((t + 3) & 3) * 1024 + k * 256 + tid,
                     W0 + (size_t)(t + 3) * 1024 + k * 256 + tid);
            CP_COMMIT();
        }
    }
}

// ---------------- formulas = y @ Wv (192 blocks, 32 rows each) -------------------
__global__ void __launch_bounds__(256) k_form(const float* __restrict__ Wv) {
    extern __shared__ float4 dyn4[];
    float4* buf = dyn4;
    float* s_in = (float*)(dyn4 + 4096);
    int e = blockIdx.x >> 5, ds = blockIdx.x & 31;
    int tid = threadIdx.x;
#pragma unroll
    for (int k = tid; k < Bb * Dm / 4; k += 256)
        reinterpret_cast<float4*>(s_in)[k] =
            reinterpret_cast<const float4*>(g_y + (size_t)e * Bb * Dm)[k];
    int d0 = ds * 32;
    const float4* W0 = reinterpret_cast<const float4*>(Wv + (size_t)e * Dm * Dm) +
                       (size_t)d0 * 256;
    float4 acc[Bb] = {};
    __syncthreads();
    gemv_streamT<8, 256>(W0, s_in, d0, buf, tid, acc);
#pragma unroll
    for (int b = 0; b < Bb; b++) {
        float* dst = g_form + ((size_t)e * Bb + b) * Dm + 4 * tid;
        atomicAdd(dst + 0, acc[b].x); atomicAdd(dst + 1, acc[b].y);
        atomicAdd(dst + 2, acc[b].z); atomicAdd(dst + 3, acc[b].w);
    }
}

// ---------------- pair projections: c[p] = [fa@Wa | fb@Wb] ----------------------
// grid = Pp*16 = 576, 128 rows each
__global__ void __launch_bounds__(256) k_pair_ab(const float* __restrict__ Wa,
                                                 const float* __restrict__ Wb) {
    extern __shared__ float4 dyn4[];
    float4* buf = dyn4;
    float* s_in = (float*)(dyn4 + 4096);
    int bid = blockIdx.x;
    int ds = bid & 7;
    int half = (bid >> 3) & 1;
    int p = bid >> 4;
    int src = half ? (p % Ee) : (p / Ee);
    int tid = threadIdx.x;
    int col = tid & 127;
#pragma unroll
    for (int k = tid; k < Bb * Dm / 4; k += 256)
        reinterpret_cast<float4*>(s_in)[k] =
            reinterpret_cast<const float4*>(g_form + (size_t)src * Bb * Dm)[k];
    int d0 = ds * 128;
    const float4* W0 = reinterpret_cast<const float4*>(
        (half ? Wb : Wa) + (size_t)p * Dm * DAa) + (size_t)d0 * 128;
    float4 acc[Bb] = {};
    __syncthreads();
    gemv_streamT<16, 128>(W0, s_in, d0, buf, tid, acc);
#pragma unroll
    for (int b = 0; b < Bb; b++) {
        float* dst = g_c + ((size_t)p * Bb + b) * 1024 + half * DAa + 4 * col;
        atomicAdd(dst + 0, acc[b].x); atomicAdd(dst + 1, acc[b].y);
        atomicAdd(dst + 2, acc[b].z); atomicAdd(dst + 3, acc[b].w);
    }
}

// ---------------- fused syn1 + gate1 --------------------------------------------
// grid = Pp*24: t<16 -> syn1 (64 rows, C4=256); t>=16 -> gate1 (128 rows, C4=128)
__global__ void __launch_bounds__(256) k_mlp1(const float* __restrict__ sW1,
                                              const float* __restrict__ gW1) {
    extern __shared__ float4 dyn4[];
    float4* buf = dyn4;
    float* s_in = (float*)(dyn4 + 4096);
    int bid = blockIdx.x;
    int t = bid % 24;
    int p = bid / 24;
    int tid = threadIdx.x;
#pragma unroll
    for (int k = tid; k < Bb * 1024 / 4; k += 256)
        reinterpret_cast<float4*>(s_in)[k] =
            reinterpret_cast<const float4*>(g_c + (size_t)p * Bb * 1024)[k];
    float4 acc[Bb] = {};
    __syncthreads();
    if (t < 16) {
        int d0 = t * 64;
        const float4* W0 = reinterpret_cast<const float4*>(sW1 + (size_t)p * 1024 * Dm) +
                           (size_t)d0 * 256;
        gemv_streamT<16, 256>(W0, s_in, d0, buf, tid, acc);
#pragma unroll
        for (int b = 0; b < Bb; b++) {
            float* dst = g_hs + ((size_t)p * Bb + b) * Dm + 4 * tid;
            atomicAdd(dst + 0, acc[b].x); atomicAdd(dst + 1, acc[b].y);
            atomicAdd(dst + 2, acc[b].z); atomicAdd(dst + 3, acc[b].w);
        }
    } else {
        int ds = t - 16;
        int col = tid & 127;
        int d0 = ds * 128;
        const float4* W0 = reinterpret_cast<const float4*>(gW1 + (size_t)p * 1024 * DAa) +
                           (size_t)d0 * 128;
        gemv_streamT<16, 128>(W0, s_in, d0, buf, tid, acc);
#pragma unroll
        for (int b = 0; b < Bb; b++) {
            float* dst = g_hpre + ((size_t)p * Bb + b) * DAa + 4 * col;
            atomicAdd(dst + 0, acc[b].x); atomicAdd(dst + 1, acc[b].y);
            atomicAdd(dst + 2, acc[b].z); atomicAdd(dst + 3, acc[b].w);
        }
    }
}

// ---------------- strength + scalepb + bias-total + aux out ---------------------
__global__ void __launch_bounds__(128) k_strength(const float* __restrict__ gW2,
                                                  const float* __restrict__ gb2,
                                                  const float* __restrict__ pg,
                                                  const float* __restrict__ sb2,
                                                  float* __restrict__ out, int out_size) {
    int p = blockIdx.x, tid = threadIdx.x;
    float part[Bb] = {0.f, 0.f, 0.f, 0.f};
    for (int a = tid; a < DAa; a += 128) {
        float w2 = gW2[p * DAa + a];
#pragma unroll
        for (int b = 0; b < Bb; b++) {
            float h = g_hpre[((size_t)p * Bb + b) * DAa + a];
            part[b] += gelu_exact(h) * w2;
        }
    }
    __shared__ float s_red[Bb][4];
    __shared__ float s_sc[Bb];
#pragma unroll
    for (int b = 0; b < Bb; b++) {
        float v = part[b];
#pragma unroll
        for (int o = 16; o; o >>= 1) v += __shfl_down_sync(0xffffffffu, v, o);
        if ((tid & 31) == 0) s_red[b][tid >> 5] = v;
    }
    __syncthreads();
    if (tid == 0) {
        float avg = 0.0f;
        float st[Bb];
#pragma unroll
        for (int b = 0; b < Bb; b++) {
            float d = s_red[b][0] + s_red[b][1] + s_red[b][2] + s_red[b][3] + gb2[p];
            st[b] = 1.0f / (1.0f + expf(-d));
            avg += st[b];
        }
        avg *= 0.25f;
        if (out_size >= OUT_MAIN + Pp + 1) out[OUT_MAIN + p] = avg;
        float mk = 0.0f;
        if (avg > THRESH) { mk = pg[p]; atomicAdd(&g_count, 1.0f); }
#pragma unroll
        for (int b = 0; b < Bb; b++) {
            float sc = mk * st[b];
            g_scalepb[p * Bb + b] = sc;
            s_sc[b] = sc;
        }
    }
    __syncthreads();
    float sc0 = s_sc[0], sc1 = s_sc[1], sc2 = s_sc[2], sc3 = s_sc[3];
    for (int j = tid; j < Dm; j += 128) {
        float bias = sb2[p * Dm + j];
        atomicAdd(&g_total[0 * Dm + j], sc0 * bias);
        atomicAdd(&g_total[1 * Dm + j], sc1 * bias);
        atomicAdd(&g_total[2 * Dm + j], sc2 * bias);
        atomicAdd(&g_total[3 * Dm + j], sc3 * bias);
    }
}

// ---------------- total += scale_pb * (gelu(hs) @ syn_W2) -----------------------
// grid = Pp*16 = 576 (64 rows each)
__global__ void __launch_bounds__(256) k_syn2(const float* __restrict__ sW2) {
    extern __shared__ float4 dyn4[];
    float4* buf = dyn4;
    float* s_in = (float*)(dyn4 + 4096);
    int bid = blockIdx.x;
    int ds = bid & 15;
    int p = bid >> 4;
    int tid = threadIdx.x;
#pragma unroll
    for (int k = tid; k < Bb * Dm / 4; k += 256) {
        float4 v = reinterpret_cast<const float4*>(g_hs + (size_t)p * Bb * Dm)[k];
        v.x = gelu_exact(v.x); v.y = gelu_exact(v.y);
        v.z = gelu_exact(v.z); v.w = gelu_exact(v.w);
        reinterpret_cast<float4*>(s_in)[k] = v;
    }
    int d0 = ds * 64;
    const float4* W0 = reinterpret_cast<const float4*>(sW2 + (size_t)p * Dm * Dm) +
                       (size_t)d0 * 256;
    float4 acc[Bb] = {};
    __syncthreads();
    gemv_streamT<16, 256>(W0, s_in, d0, buf, tid, acc);
#pragma unroll
    for (int b = 0; b < Bb; b++) {
        float sc = g_scalepb[p * Bb + b];
        float* dst = g_total + b * Dm + 4 * tid;
        atomicAdd(dst + 0, acc[b].x * sc); atomicAdd(dst + 1, acc[b].y * sc);
        atomicAdd(dst + 2, acc[b].z * sc); atomicAdd(dst + 3, acc[b].w * sc);
    }
}

// ---------------- fused LN + projection ------------------------------------------
__global__ void __launch_bounds__(256) k_ln_proj(const float* __restrict__ gamma,
                                                 const float* __restrict__ beta,
                                                 const float* __restrict__ out_W,
                                                 const float* __restrict__ ag_p,
                                                 float* __restrict__ out, int out_size) {
    int ds = blockIdx.x;
    int tid = threadIdx.x;
    __shared__ float s_norm[Bb * Dm];
    __shared__ float s_red[8];
    __shared__ float s_stat;
    float inv_cnt = 1.0f / fmaxf(g_count, 1.0f);
    float ag = *ag_p;
    if (ds == 0 && tid == 0 && out_size >= OUT_MAIN + Pp + 1)
        out[OUT_MAIN + Pp] = g_count;
    float4 ga = reinterpret_cast<const float4*>(gamma)[tid];
    float4 be = reinterpret_cast<const float4*>(beta)[tid];
    for (int b = 0; b < Bb; b++) {
        float4 v = reinterpret_cast<const float4*>(g_total + b * Dm)[tid];
        v.x *= inv_cnt; v.y *= inv_cnt; v.z *= inv_cnt; v.w *= inv_cnt;
        float lsum = v.x + v.y + v.z + v.w;
#pragma unroll
        for (int o = 16; o; o >>= 1) lsum += __shfl_down_sync(0xffffffffu, lsum, o);
        if ((tid & 31) == 0) s_red[tid >> 5] = lsum;
        __syncthreads();
        if (tid == 0) {
            float t = 0;
#pragma unroll
            for (int k = 0; k < 8; k++) t += s_red[k];
            s_stat = t * (1.0f / Dm);
        }
        __syncthreads();
        float mu = s_stat;
        __syncthreads();
        float dx = v.x - mu, dy = v.y - mu, dz = v.z - mu, dw = v.w - mu;
        float lsq = dx * dx + dy * dy + dz * dz + dw * dw;
#pragma unroll
        for (int o = 16; o; o >>= 1) lsq += __shfl_xor_sync(0xffffffffu, lsq, o);
        if ((tid & 31) == 0) s_red[tid >> 5] = lsq;
        __syncthreads();
        if (tid == 0) {
            float t = 0;
#pragma unroll
            for (int k = 0; k < 8; k++) t += s_red[k];
            s_stat = t * (1.0f / Dm);
        }
        __syncthreads();
        float rstd = rsqrtf(s_stat + LN_EPS);
        __syncthreads();
        float4 nv;
        nv.x = dx * rstd * ga.x + be.x;
        nv.y = dy * rstd * ga.y + be.y;
        nv.z = dz * rstd * ga.z + be.z;
        nv.w = dw * rstd * ga.w + be.w;
        reinterpret_cast<float4*>(s_norm + b * Dm)[tid] = nv;
    }
    __syncthreads();
    const float4* Wp = reinterpret_cast<const float4*>(out_W) +
                       (size_t)(ds * 32) * 256 + tid;
    float4 acc[Bb] = {};
#pragma unroll 4
    for (int dd = 0; dd < 32; dd++) {
        float4 w = Wp[(size_t)dd * 256];
#pragma unroll
        for (int b = 0; b < Bb; b++) {
            float x = s_norm[b * Dm + ds * 32 + dd];
            acc[b].x += x * w.x; acc[b].y += x * w.y;
            acc[b].z += x * w.z; acc[b].w += x * w.w;
        }
    }
#pragma unroll
    for (int b = 0; b < Bb; b++) {
        float* dst = g_addition + b * Dm + 4 * tid;
        atomicAdd(dst + 0, acc[b].x * ag); atomicAdd(dst + 1, acc[b].y * ag);
        atomicAdd(dst + 2, acc[b].z * ag); atomicAdd(dst + 3, acc[b].w * ag);
    }
}

// ---------------- output = bridge + addition -------------------------------------
__global__ void __launch_bounds__(256) k_output(const float* __restrict__ bridge,
                                                float* __restrict__ out) {
    size_t i4 = (size_t)blockIdx.x * 256 + threadIdx.x;
    if (i4 >= (size_t)OUT_MAIN / 4) return;
    float4 br = reinterpret_cast<const float4*>(bridge)[i4];
    int b = (int)(i4 >> 19);
    int d4 = (int)(i4 & 255);
    if (g_count > 0.0f) {
        float4 ad = reinterpret_cast<const float4*>(g_addition)[b * 256 + d4];
        br.x += ad.x; br.y += ad.y; br.z += ad.z; br.w += ad.w;
    }
    reinterpret_cast<float4*>(out)[i4] = br;
}

// ---------------- launch ----------------------------------------------------------
extern "C" void kernel_launch(void* const* d_in, const int* in_sizes, int n_in,
                              void* d_out, int out_size) {
    const float* bridge = (const float*)d_in[0];
    const float* eo     = (const float*)d_in[1];
    const float* ew     = (const float*)d_in[2];
    const float* q      = (const float*)d_in[3];
    const float* Wk     = (const float*)d_in[4];
    const float* Wv     = (const float*)d_in[6];
    const float* bv     = (const float*)d_in[7];
    const float* Wa     = (const float*)d_in[8];
    const float* ba     = (const float*)d_in[9];
    const float* Wb     = (const float*)d_in[10];
    const float* bb     = (const float*)d_in[11];
    const float* gW1    = (const float*)d_in[12];
    const float* gb1    = (const float*)d_in[13];
    const float* gW2    = (const float*)d_in[14];
    const float* gb2    = (const float*)d_in[15];
    const float* sW1    = (const float*)d_in[16];
    const float* sb1    = (const float*)d_in[17];
    const float* sW2    = (const float*)d_in[18];
    const float* sb2    = (const float*)d_in[19];
    const float* pg     = (const float*)d_in[20];
    const float* gamma  = (const float*)d_in[21];
    const float* beta   = (const float*)d_in[22];
    const float* outW   = (const float*)d_in[23];
    const float* outb   = (const float*)d_in[24];
    const float* agate  = (const float*)d_in[25];
    float* out = (float*)d_out;

    cudaFuncSetAttribute(k_condense, cudaFuncAttributeMaxDynamicSharedMemorySize, COND_SMEM);
    cudaFuncSetAttribute(k_form,     cudaFuncAttributeMaxDynamicSharedMemorySize, STRM_SMEM);
    cudaFuncSetAttribute(k_pair_ab,  cudaFuncAttributeMaxDynamicSharedMemorySize, STRM_SMEM);
    cudaFuncSetAttribute(k_mlp1,     cudaFuncAttributeMaxDynamicSharedMemorySize, STRM_SMEM);
    cudaFuncSetAttribute(k_syn2,     cudaFuncAttributeMaxDynamicSharedMemorySize, STRM_SMEM);

    k_init_u<<<INIT_BLOCKS + U_BLOCKS, 256>>>(bv, ba, bb, gb1, sb1, outb, agate, Wk, q);
    k_condense<<<Ee * Bb * NCHUNK, 256, COND_SMEM>>>(eo, ew);
    k_combine<<<Ee * Bb * 8, 256>>>();
    k_form<<<Ee * 32, 256, STRM_SMEM>>>(Wv);
    k_pair_ab<<<Pp * 16, 256, STRM_SMEM>>>(Wa, Wb);
    k_mlp1<<<Pp * 24, 256, STRM_SMEM>>>(sW1, gW1);
    k_strength<<<Pp, 128>>>(gW2, gb2, pg, sb2, out, out_size);
    k_syn2<<<Pp * 16, 256, STRM_SMEM>>>(sW2);
    k_ln_proj<<<32, 256>>>(gamma, beta, outW, agate, out, out_size);
    k_output<<<(OUT_MAIN / 4 + 255) / 256, 256>>>(bridge, out);
}